// round 3
// baseline (speedup 1.0000x reference)
#include <cuda_runtime.h>
#include <cstdint>

#define B_ 16
#define N_ 2048
#define D_ 256
#define K_ 8
#define H_ 4
#define ITERS_ 3
#define HID_ 1024
#define SCALE_ 0.0625f
#define EPS_ 1e-5f
#define PAIRS_ (B_*K_)          // 128

// ---- scratch (device globals; no allocations allowed) ----
__device__ float g_emb[B_*N_*D_];           // 32 MiB  LN(embeddings)
__device__ float g_wk[B_*K_*H_*D_];         // 512 KiB query-folded key proj
__device__ float g_cpart[32*PAIRS_*D_];     // 4 MiB   per-tile partial c sums
__device__ float g_xs[PAIRS_*D_];           // GRU input x (= upd)
__device__ float g_sn[PAIRS_*D_];           // GRU output (pre-LN)
__device__ float g_hid[PAIRS_*HID_];        // MLP hidden
__device__ float g_part[4*PAIRS_*D_];       // MLP2 K-split partials
__device__ float g_wihT[D_*3*D_];           // wih^T (256 x 768)
__device__ float g_whhT[D_*3*D_];           // whh^T (256 x 768)
__device__ float g_w1T[D_*HID_];            // w1^T  (256 x 1024)
__device__ float g_w2T[HID_*D_];            // w2^T  (1024 x 256)

typedef unsigned long long ull;

// packed f32x2 helpers (Blackwell FFMA2 — PTX-only pattern)
#define FMA2(d, a, b) asm("fma.rn.f32x2 %0, %1, %2, %0;" : "+l"(d) : "l"(a), "l"(b))
#define PACK2(out, lo, hi) asm("mov.b64 %0, {%1, %2};" : "=l"(out) : "r"(__float_as_uint(lo)), "r"(__float_as_uint(hi)))
__device__ __forceinline__ void unpack2(ull v, float& lo, float& hi){
    unsigned int a, b;
    asm("mov.b64 {%0, %1}, %2;" : "=r"(a), "=r"(b) : "l"(v));
    lo = __uint_as_float(a); hi = __uint_as_float(b);
}

__device__ __forceinline__ float warpSum(float v){
#pragma unroll
    for (int o = 16; o > 0; o >>= 1) v += __shfl_xor_sync(0xffffffffu, v, o);
    return v;
}

// ---------------------------------------------------------------------------
// slots = mu + exp(logsigma) * noise
// ---------------------------------------------------------------------------
__global__ void k_init(const float* __restrict__ mu, const float* __restrict__ ls,
                       const float* __restrict__ noise, float* __restrict__ slots){
    int i = blockIdx.x * blockDim.x + threadIdx.x;
    int j = i & (K_*D_ - 1);
    slots[i] = mu[j] + expf(ls[j]) * noise[i];
}

// ---------------------------------------------------------------------------
// Tiled transpose: out[C][R] = in[R][C].  grid dim3(C/32, R/32), block (32,8).
// ---------------------------------------------------------------------------
__global__ void k_transpose(const float* __restrict__ in, float* __restrict__ out,
                            int R, int C){
    __shared__ float t[32][33];
    int c0 = blockIdx.x * 32, r0 = blockIdx.y * 32;
    int x = threadIdx.x, y = threadIdx.y;
    for (int i = y; i < 32; i += 8) t[i][x] = in[(size_t)(r0 + i) * C + c0 + x];
    __syncthreads();
    for (int i = y; i < 32; i += 8) out[(size_t)(c0 + i) * R + r0 + x] = t[x][i];
}

// ---------------------------------------------------------------------------
// g_emb = LayerNorm(embeddings)*g + b   (warp per row)
// ---------------------------------------------------------------------------
__global__ void k_ln_emb(const float* __restrict__ x, const float* __restrict__ g,
                         const float* __restrict__ bb){
    int row  = blockIdx.x * 8 + (threadIdx.x >> 5);
    int lane = threadIdx.x & 31;
    const float4* xr = (const float4*)(x + (size_t)row * D_);
    float4 a = xr[lane], c = xr[lane + 32];
    float s = a.x+a.y+a.z+a.w + c.x+c.y+c.z+c.w;
    float q = a.x*a.x+a.y*a.y+a.z*a.z+a.w*a.w + c.x*c.x+c.y*c.y+c.z*c.z+c.w*c.w;
    s = warpSum(s); q = warpSum(q);
    float m = s * (1.0f / D_);
    float r = rsqrtf(q * (1.0f / D_) - m*m + EPS_);
    float4 ga = ((const float4*)g)[lane],  gc = ((const float4*)g)[lane + 32];
    float4 ba = ((const float4*)bb)[lane], bc = ((const float4*)bb)[lane + 32];
    float4 oa, oc;
    oa.x = (a.x-m)*r*ga.x + ba.x;  oa.y = (a.y-m)*r*ga.y + ba.y;
    oa.z = (a.z-m)*r*ga.z + ba.z;  oa.w = (a.w-m)*r*ga.w + ba.w;
    oc.x = (c.x-m)*r*gc.x + bc.x;  oc.y = (c.y-m)*r*gc.y + bc.y;
    oc.z = (c.z-m)*r*gc.z + bc.z;  oc.w = (c.w-m)*r*gc.w + bc.w;
    float4* orow = (float4*)(g_emb + (size_t)row * D_);
    orow[lane] = oa;  orow[lane + 32] = oc;
}

// ---------------------------------------------------------------------------
// per (b,k): s = LN(slots); q = s*diag(tq[k]); wk[b,k,h,e] = sum_{d in h} tk[k,e,d]*q[d]
// ---------------------------------------------------------------------------
__global__ void k_slotproj(const float* __restrict__ slots, const float* __restrict__ tq,
                           const float* __restrict__ tk,
                           const float* __restrict__ lng, const float* __restrict__ lnb){
    __shared__ float qs[D_];
    __shared__ float red[32];
    int blk = blockIdx.x;                 // p = b*8 + k
    int b = blk >> 3, k = blk & 7;
    int tid = threadIdx.x, lane = tid & 31, w = tid >> 5;

    float x = slots[(size_t)blk * D_ + tid];
    float s = warpSum(x), q2 = warpSum(x * x);
    if (lane == 0){ red[w] = s; red[8 + w] = q2; }
    __syncthreads();
    if (tid == 0){
        float ts = 0.f, tqq = 0.f;
        for (int i = 0; i < 8; i++){ ts += red[i]; tqq += red[8 + i]; }
        float m = ts * (1.0f / D_);
        red[16] = m;
        red[17] = rsqrtf(tqq * (1.0f / D_) - m*m + EPS_);
    }
    __syncthreads();
    float m = red[16], r = red[17];
    float sv = (x - m) * r * lng[tid] + lnb[tid];
    qs[tid] = sv * tq[(size_t)k * D_ * D_ + (size_t)tid * D_ + tid];   // diagonal
    __syncthreads();

    const float* tkk = tk + (size_t)k * D_ * D_;
    for (int ei = 0; ei < 32; ei++){
        int e = w * 32 + ei;
        const float* te = tkk + (size_t)e * D_;
        float p0 = 0.f, p1 = 0.f, p2 = 0.f, p3 = 0.f;
#pragma unroll
        for (int j = 0; j < 8; j++){
            int d = j * 32 + lane;                 // each j lies inside one head
            float v = te[d] * qs[d];
            if (j < 2) p0 += v; else if (j < 4) p1 += v; else if (j < 6) p2 += v; else p3 += v;
        }
        p0 = warpSum(p0); p1 = warpSum(p1); p2 = warpSum(p2); p3 = warpSum(p3);
        if (lane == 0){
            float* wo = g_wk + (size_t)b * 32 * D_ + (size_t)(k * 4) * D_ + e;
            wo[0] = p0; wo[D_] = p1; wo[2 * D_] = p2; wo[3 * D_] = p3;
        }
    }
}

// ---------------------------------------------------------------------------
// fused dots -> softmax over slots -> head-avg -> attn_vis; per-tile c partials.
// Block: 256 thr, 64 tokens; lane owns kh = k*4+h. Packed-f32x2 inner loops.
// ---------------------------------------------------------------------------
#define TPB 64
#define WPITCH 260
#define APITCH 10

__global__ void __launch_bounds__(256, 2) k_attn(float* __restrict__ attnv){
    extern __shared__ float sm[];
    float* wks  = sm;                       // 32 x 260
    float* embs = sm + 32 * WPITCH;         // 64 x 256
    float* a_s  = embs + TPB * D_;          // 64 x 10 (8B-aligned rows)

    int b    = blockIdx.x >> 5;
    int tile = blockIdx.x & 31;
    int n0   = tile * TPB;
    int tid = threadIdx.x, lane = tid & 31, w = tid >> 5;

    const float* wg = g_wk + (size_t)b * 32 * D_;
    for (int i = tid; i < 32 * D_; i += 256)
        wks[(i >> 8) * WPITCH + (i & 255)] = wg[i];
    const float4* eg = (const float4*)(g_emb + ((size_t)b * N_ + n0) * D_);
    float4* es4 = (float4*)embs;
    for (int i = tid; i < TPB * D_ / 4; i += 256) es4[i] = eg[i];
    __syncthreads();

    // phase 1: dots, packed over e-pairs
    ull acc[8] = {0,0,0,0,0,0,0,0};
    const float* wrow = wks + lane * WPITCH;
    const float* erow = embs + (w * 8) * D_;
    for (int e = 0; e < D_; e += 4){
        ulonglong2 wv = *(const ulonglong2*)(wrow + e);
#pragma unroll
        for (int j = 0; j < 8; j++){
            ulonglong2 ev = *(const ulonglong2*)(erow + j * D_ + e);
            FMA2(acc[j], wv.x, ev.x);
            FMA2(acc[j], wv.y, ev.y);
        }
    }
    int k = lane >> 2;
#pragma unroll
    for (int j = 0; j < 8; j++){
        float lo, hi;  unpack2(acc[j], lo, hi);
        float d = (lo + hi) * SCALE_;
        float mm = d;
        mm = fmaxf(mm, __shfl_xor_sync(0xffffffffu, mm, 4));
        mm = fmaxf(mm, __shfl_xor_sync(0xffffffffu, mm, 8));
        mm = fmaxf(mm, __shfl_xor_sync(0xffffffffu, mm, 16));
        float p = __expf(d - mm);
        float ssum = p;
        ssum += __shfl_xor_sync(0xffffffffu, ssum, 4);
        ssum += __shfl_xor_sync(0xffffffffu, ssum, 8);
        ssum += __shfl_xor_sync(0xffffffffu, ssum, 16);
        float af = p / ssum;                       // softmax over slots k
        af += __shfl_xor_sync(0xffffffffu, af, 1);
        af += __shfl_xor_sync(0xffffffffu, af, 2); // sum over heads
        if ((lane & 3) == 0) a_s[(w * 8 + j) * APITCH + k] = af * 0.25f;
    }
    __syncthreads();

    // attn_vis
    float* av = attnv + (size_t)b * K_ * N_ + n0;
    for (int i = tid; i < K_ * TPB; i += 256){
        int kk = i >> 6, t = i & 63;
        av[(size_t)kk * N_ + t] = a_s[t * APITCH + kk];
    }

    // phase 2: per-tile partial c; warp w owns e = w*32+lane; packed over k-pairs
    int e = w * 32 + lane;
    ull cl2[4] = {0,0,0,0};
    for (int t = 0; t < TPB; t++){
        float ev = embs[t * D_ + e];
        ull ev2;  PACK2(ev2, ev, ev);
        const ull* ar = (const ull*)(a_s + t * APITCH);
        FMA2(cl2[0], ar[0], ev2);
        FMA2(cl2[1], ar[1], ev2);
        FMA2(cl2[2], ar[2], ev2);
        FMA2(cl2[3], ar[3], ev2);
    }
    float* cp = g_cpart + (size_t)tile * (PAIRS_*D_) + (size_t)b * K_ * D_ + e;
#pragma unroll
    for (int m = 0; m < 4; m++){
        float lo, hi;  unpack2(cl2[m], lo, hi);
        cp[(size_t)(2*m) * D_]     = lo;
        cp[(size_t)(2*m + 1) * D_] = hi;
    }
}

// ---------------------------------------------------------------------------
// k_prep: pairs {p, p+64} (same k): rowsum; cn = (sum of tile partials)/rs;
//         xs = cn @ tv[k].
// ---------------------------------------------------------------------------
__global__ void __launch_bounds__(256) k_prep(const float* __restrict__ attnv,
                                              const float* __restrict__ tv){
    __shared__ float cn[2][D_];
    __shared__ float red[34];
    int tid = threadIdx.x, lane = tid & 31, w = tid >> 5;
    int pA = blockIdx.x, pB = blockIdx.x + 64;
    int k = pA & 7;

    float rs[2];
#pragma unroll
    for (int bb = 0; bb < 2; bb++){
        const float* a = attnv + (size_t)(bb ? pB : pA) * N_;
        float s = 0.f;
        for (int i = tid; i < N_; i += 256) s += a[i];
        s = warpSum(s);
        if (lane == 0) red[w] = s;
        __syncthreads();
        if (tid == 0){ float t = 0.f; for (int i = 0; i < 8; i++) t += red[i]; red[32] = t; }
        __syncthreads();
        rs[bb] = red[32];
        __syncthreads();
    }
    float c0 = 0.f, c1 = 0.f;
    for (int t = 0; t < 32; t++){
        c0 += g_cpart[(size_t)t * (PAIRS_*D_) + (size_t)pA * D_ + tid];
        c1 += g_cpart[(size_t)t * (PAIRS_*D_) + (size_t)pB * D_ + tid];
    }
    cn[0][tid] = c0 / rs[0];
    cn[1][tid] = c1 / rs[1];
    __syncthreads();

    float x0 = 0.f, x1 = 0.f;
    const float* tvk = tv + (size_t)k * D_ * D_ + tid;
#pragma unroll 4
    for (int e = 0; e < D_; e++){
        float t = tvk[(size_t)e * D_];
        x0 += cn[0][e] * t;  x1 += cn[1][e] * t;
    }
    g_xs[(size_t)pA * D_ + tid] = x0;
    g_xs[(size_t)pB * D_ + tid] = x1;
}

// ---------------------------------------------------------------------------
// k_gates: grid 128 = (16 groups of 8 pairs) x (8 d-tiles of 32).
// thread (bb = tid>>5, d = d0 + lane) computes full GRU output sn at (pair, d).
// ---------------------------------------------------------------------------
__global__ void __launch_bounds__(256) k_gates(const float* __restrict__ slots,
                                               const float* __restrict__ bih,
                                               const float* __restrict__ bhh){
    __shared__ float xs[8][D_];
    __shared__ float hs[8][D_];
    int g  = blockIdx.x >> 3;
    int d0 = (blockIdx.x & 7) * 32;
    int tid = threadIdx.x;
    for (int i = tid; i < 8 * D_; i += 256){
        int pp = i >> 8, e = i & 255;
        xs[pp][e] = g_xs[(size_t)(g * 8 + pp) * D_ + e];
        hs[pp][e] = slots[(size_t)(g * 8 + pp) * D_ + e];
    }
    __syncthreads();

    int bb = tid >> 5, d = d0 + (tid & 31);
    float gi0 = bih[d], gi1 = bih[d + D_], gi2 = bih[d + 2*D_];
    float gh0 = bhh[d], gh1 = bhh[d + D_], gh2 = bhh[d + 2*D_];
    const float* wi = g_wihT + d;
    const float* wh = g_whhT + d;
#pragma unroll 4
    for (int e = 0; e < D_; e++){
        float xv = xs[bb][e], hv = hs[bb][e];
        const float* wie = wi + (size_t)e * (3*D_);
        const float* whe = wh + (size_t)e * (3*D_);
        gi0 += wie[0] * xv;  gi1 += wie[D_] * xv;  gi2 += wie[2*D_] * xv;
        gh0 += whe[0] * hv;  gh1 += whe[D_] * hv;  gh2 += whe[2*D_] * hv;
    }
    float r = 1.f / (1.f + __expf(-(gi0 + gh0)));
    float z = 1.f / (1.f + __expf(-(gi1 + gh1)));
    float n = tanhf(gi2 + r * gh2);
    g_sn[(size_t)(g * 8 + bb) * D_ + d] = (1.f - z) * n + z * hs[bb][d];
}

// ---------------------------------------------------------------------------
// k_mlp1: grid 64 = 16 groups x 4 h-tiles(256). In-block LN_ff of the 8 rows,
// then hidden GEMM (packed f32x2) + ReLU -> g_hid.
// ---------------------------------------------------------------------------
__global__ void __launch_bounds__(256) k_mlp1(const float* __restrict__ b1v,
                                              const float* __restrict__ ffg,
                                              const float* __restrict__ ffb){
    __shared__ __align__(16) float ps[8][D_];
    int g  = blockIdx.x >> 2;
    int h0 = (blockIdx.x & 3) * 256;
    int tid = threadIdx.x, lane = tid & 31, w = tid >> 5;

    // warp w LayerNorms row (g*8 + w)
    {
        const float4* xr = (const float4*)(g_sn + (size_t)(g * 8 + w) * D_);
        float4 a = xr[lane], c = xr[lane + 32];
        float s = a.x+a.y+a.z+a.w + c.x+c.y+c.z+c.w;
        float q = a.x*a.x+a.y*a.y+a.z*a.z+a.w*a.w + c.x*c.x+c.y*c.y+c.z*c.z+c.w*c.w;
        s = warpSum(s); q = warpSum(q);
        float m = s * (1.0f / D_);
        float r = rsqrtf(q * (1.0f / D_) - m*m + EPS_);
        float4 ga = ((const float4*)ffg)[lane],  gc = ((const float4*)ffg)[lane + 32];
        float4 ba = ((const float4*)ffb)[lane],  bc = ((const float4*)ffb)[lane + 32];
        float4 oa, oc;
        oa.x = (a.x-m)*r*ga.x + ba.x;  oa.y = (a.y-m)*r*ga.y + ba.y;
        oa.z = (a.z-m)*r*ga.z + ba.z;  oa.w = (a.w-m)*r*ga.w + ba.w;
        oc.x = (c.x-m)*r*gc.x + bc.x;  oc.y = (c.y-m)*r*gc.y + bc.y;
        oc.z = (c.z-m)*r*gc.z + bc.z;  oc.w = (c.w-m)*r*gc.w + bc.w;
        ((float4*)ps[w])[lane] = oa;  ((float4*)ps[w])[lane + 32] = oc;
    }
    __syncthreads();

    int h = h0 + tid;
    ull acc2[8] = {0,0,0,0,0,0,0,0};
    const float* w1c = g_w1T + h;
    for (int e4 = 0; e4 < 64; e4++){
        int e = e4 * 4;
        float w0 = w1c[(size_t)e * HID_],       w1v = w1c[(size_t)(e+1) * HID_];
        float w2v = w1c[(size_t)(e+2) * HID_],  w3v = w1c[(size_t)(e+3) * HID_];
        ull w01, w23;  PACK2(w01, w0, w1v);  PACK2(w23, w2v, w3v);
#pragma unroll
        for (int pp = 0; pp < 8; pp++){
            ulonglong2 pv = ((const ulonglong2*)ps[pp])[e4];
            FMA2(acc2[pp], w01, pv.x);
            FMA2(acc2[pp], w23, pv.y);
        }
    }
    float bv = b1v[h];
#pragma unroll
    for (int pp = 0; pp < 8; pp++){
        float lo, hi;  unpack2(acc2[pp], lo, hi);
        g_hid[(size_t)(g * 8 + pp) * HID_ + h] = fmaxf(lo + hi + bv, 0.f);
    }
}

// ---------------------------------------------------------------------------
// k_mlp2: grid 64 = 16 groups x 4 K-splits(256). Partials -> g_part (deterministic).
// ---------------------------------------------------------------------------
__global__ void __launch_bounds__(256) k_mlp2(){
    __shared__ __align__(16) float hd[8][D_];
    int g  = blockIdx.x >> 2;
    int ks = blockIdx.x & 3;
    int e0 = ks * 256;
    int tid = threadIdx.x;
    for (int i = tid; i < 8 * D_; i += 256){
        int pp = i >> 8, e = i & 255;
        hd[pp][e] = g_hid[(size_t)(g * 8 + pp) * HID_ + e0 + e];
    }
    __syncthreads();

    int d = tid;
    ull acc2[8] = {0,0,0,0,0,0,0,0};
    const float* w2c = g_w2T + (size_t)e0 * D_ + d;
    for (int e4 = 0; e4 < 64; e4++){
        int e = e4 * 4;
        float w0 = w2c[(size_t)e * D_],       w1v = w2c[(size_t)(e+1) * D_];
        float w2v = w2c[(size_t)(e+2) * D_],  w3v = w2c[(size_t)(e+3) * D_];
        ull w01, w23;  PACK2(w01, w0, w1v);  PACK2(w23, w2v, w3v);
#pragma unroll
        for (int pp = 0; pp < 8; pp++){
            ulonglong2 hv = ((const ulonglong2*)hd[pp])[e4];
            FMA2(acc2[pp], w01, hv.x);
            FMA2(acc2[pp], w23, hv.y);
        }
    }
#pragma unroll
    for (int pp = 0; pp < 8; pp++){
        float lo, hi;  unpack2(acc2[pp], lo, hi);
        g_part[(size_t)ks * (PAIRS_*D_) + (size_t)(g * 8 + pp) * D_ + d] = lo + hi;
    }
}

// ---------------------------------------------------------------------------
// k_fin: slots = sn + b2 + sum of 4 MLP2 partials
// ---------------------------------------------------------------------------
__global__ void k_fin(float* __restrict__ slots, const float* __restrict__ b2v){
    int p = blockIdx.x, d = threadIdx.x;
    size_t i = (size_t)p * D_ + d;
    float v = g_sn[i] + b2v[d];
    v += g_part[i];
    v += g_part[(size_t)(PAIRS_*D_) + i];
    v += g_part[(size_t)2*(PAIRS_*D_) + i];
    v += g_part[(size_t)3*(PAIRS_*D_) + i];
    slots[i] = v;
}

// ---------------------------------------------------------------------------
extern "C" void kernel_launch(void* const* d_in, const int* in_sizes, int n_in,
                              void* d_out, int out_size){
    const float* emb  = (const float*)d_in[0];
    const float* noise= (const float*)d_in[1];
    const float* mu   = (const float*)d_in[2];
    const float* ls   = (const float*)d_in[3];
    const float* tk   = (const float*)d_in[4];
    const float* tq   = (const float*)d_in[5];
    const float* tv   = (const float*)d_in[6];
    const float* wih  = (const float*)d_in[7];
    const float* whh  = (const float*)d_in[8];
    const float* bih  = (const float*)d_in[9];
    const float* bhh  = (const float*)d_in[10];
    const float* w1   = (const float*)d_in[11];
    const float* b1   = (const float*)d_in[12];
    const float* w2   = (const float*)d_in[13];
    const float* b2   = (const float*)d_in[14];
    const float* ling = (const float*)d_in[15];
    const float* linb = (const float*)d_in[16];
    const float* lslg = (const float*)d_in[17];
    const float* lslb = (const float*)d_in[18];
    const float* lffg = (const float*)d_in[19];
    const float* lffb = (const float*)d_in[20];

    float* slots = (float*)d_out;               // (B,K,D)
    float* attnv = slots + B_*K_*D_;            // (B,K,N)

    const int smemB = (32 * WPITCH + TPB * D_ + TPB * APITCH) * 4;   // ~99 KB
    cudaFuncSetAttribute(k_attn, cudaFuncAttributeMaxDynamicSharedMemorySize, smemB);

    float *wihT, *whhT, *w1T, *w2T;
    cudaGetSymbolAddress((void**)&wihT, g_wihT);
    cudaGetSymbolAddress((void**)&whhT, g_whhT);
    cudaGetSymbolAddress((void**)&w1T,  g_w1T);
    cudaGetSymbolAddress((void**)&w2T,  g_w2T);

    k_init<<<(B_*K_*D_)/256, 256>>>(mu, ls, noise, slots);
    k_transpose<<<dim3(D_/32, 3*D_/32), dim3(32,8)>>>(wih, wihT, 3*D_, D_);
    k_transpose<<<dim3(D_/32, 3*D_/32), dim3(32,8)>>>(whh, whhT, 3*D_, D_);
    k_transpose<<<dim3(D_/32, HID_/32), dim3(32,8)>>>(w1, w1T, HID_, D_);
    k_transpose<<<dim3(HID_/32, D_/32), dim3(32,8)>>>(w2, w2T, D_, HID_);
    k_ln_emb<<<B_*N_/8, 256>>>(emb, ling, linb);

    for (int it = 0; it < ITERS_; it++){
        k_slotproj<<<B_*K_, 256>>>(slots, tq, tk, lslg, lslb);
        k_attn<<<B_*32, 256, smemB>>>(attnv);
        k_prep<<<64, 256>>>(attnv, tv);
        k_gates<<<128, 256>>>(slots, bih, bhh);
        k_mlp1<<<64, 256>>>(b1, lffg, lffb);
        k_mlp2<<<64, 256>>>();
        k_fin<<<128, 256>>>(slots, b2);
    }
}

// round 4
// speedup vs baseline: 1.2556x; 1.2556x over previous
#include <cuda_runtime.h>
#include <cstdint>

#define B_ 16
#define N_ 2048
#define D_ 256
#define K_ 8
#define H_ 4
#define ITERS_ 3
#define HID_ 1024
#define SCALE_ 0.0625f
#define EPS_ 1e-5f
#define PAIRS_ (B_*K_)          // 128
#define NTILES_ 32              // token tiles per batch (2048/64)

// ---- scratch (device globals; no allocations allowed) ----
__device__ float g_emb[B_*N_*D_];            // 32 MiB  LN(embeddings)
__device__ float g_wk[B_*K_*H_*D_];          // 512 KiB query-folded key proj
__device__ float g_cpart[NTILES_*PAIRS_*D_]; // 4 MiB   per-tile partial c sums
__device__ float g_rspart[B_*NTILES_*K_];    // per-tile rowsum partials
__device__ float g_xs[PAIRS_*D_];            // GRU input x (= upd)
__device__ float g_sn[PAIRS_*D_];            // GRU output (pre-LN)
__device__ float g_hid[PAIRS_*HID_];         // MLP hidden
__device__ float g_part[8*PAIRS_*D_];        // MLP2 e-split partials (deterministic)
// packed weights (float4 per entry)
__device__ float4 g_wihP[D_*D_];             // [e][d] = (ih_g0, ih_g1, ih_g2, 0)
__device__ float4 g_whhP[D_*D_];             // [e][d] = (hh_g0, hh_g1, hh_g2, 0)
__device__ float4 g_w1P[(D_/4)*HID_];        // [e4][h] = w1[h][4e4..4e4+3]
__device__ float4 g_w2P[(HID_/4)*D_];        // [e4][d] = w2[d][4e4..4e4+3]
__device__ float4 g_tvP[K_*(D_/4)*D_];       // [k][e4][d] = tv[k][4e4..][d]

typedef unsigned long long ull;

#define FMA2(d, a, b) asm("fma.rn.f32x2 %0, %1, %2, %0;" : "+l"(d) : "l"(a), "l"(b))
#define PACK2(out, lo, hi) asm("mov.b64 %0, {%1, %2};" : "=l"(out) : "r"(__float_as_uint(lo)), "r"(__float_as_uint(hi)))
__device__ __forceinline__ void unpack2(ull v, float& lo, float& hi){
    unsigned int a, b;
    asm("mov.b64 {%0, %1}, %2;" : "=r"(a), "=r"(b) : "l"(v));
    lo = __uint_as_float(a); hi = __uint_as_float(b);
}

__device__ __forceinline__ float warpSum(float v){
#pragma unroll
    for (int o = 16; o > 0; o >>= 1) v += __shfl_xor_sync(0xffffffffu, v, o);
    return v;
}

// ---------------------------------------------------------------------------
// Setup A: LN(embeddings) -> g_emb  (blocks 0..4095, 8 rows each)
//          slots init              (blocks 4096..4223)
// ---------------------------------------------------------------------------
__global__ void k_setup_a(const float* __restrict__ x, const float* __restrict__ g,
                          const float* __restrict__ bb,
                          const float* __restrict__ mu, const float* __restrict__ ls,
                          const float* __restrict__ noise, float* __restrict__ slots){
    if (blockIdx.x >= 4096){
        int i = (blockIdx.x - 4096) * 256 + threadIdx.x;
        int j = i & (K_*D_ - 1);
        slots[i] = mu[j] + expf(ls[j]) * noise[i];
        return;
    }
    int row  = blockIdx.x * 8 + (threadIdx.x >> 5);
    int lane = threadIdx.x & 31;
    const float4* xr = (const float4*)(x + (size_t)row * D_);
    float4 a = xr[lane], c = xr[lane + 32];
    float s = a.x+a.y+a.z+a.w + c.x+c.y+c.z+c.w;
    float q = a.x*a.x+a.y*a.y+a.z*a.z+a.w*a.w + c.x*c.x+c.y*c.y+c.z*c.z+c.w*c.w;
    s = warpSum(s); q = warpSum(q);
    float m = s * (1.0f / D_);
    float r = rsqrtf(q * (1.0f / D_) - m*m + EPS_);
    float4 ga = ((const float4*)g)[lane],  gc = ((const float4*)g)[lane + 32];
    float4 ba = ((const float4*)bb)[lane], bc = ((const float4*)bb)[lane + 32];
    float4 oa, oc;
    oa.x = (a.x-m)*r*ga.x + ba.x;  oa.y = (a.y-m)*r*ga.y + ba.y;
    oa.z = (a.z-m)*r*ga.z + ba.z;  oa.w = (a.w-m)*r*ga.w + ba.w;
    oc.x = (c.x-m)*r*gc.x + bc.x;  oc.y = (c.y-m)*r*gc.y + bc.y;
    oc.z = (c.z-m)*r*gc.z + bc.z;  oc.w = (c.w-m)*r*gc.w + bc.w;
    float4* orow = (float4*)(g_emb + (size_t)row * D_);
    orow[lane] = oa;  orow[lane + 32] = oc;
}

// ---------------------------------------------------------------------------
// Setup B: pack weights into float4 layouts.
// sections: [0,256) wihP  [256,512) whhP  [512,768) w1P  [768,1024) w2P
//           [1024,1536) tvP
// ---------------------------------------------------------------------------
__global__ void k_setup_pack(const float* __restrict__ wih, const float* __restrict__ whh,
                             const float* __restrict__ w1, const float* __restrict__ w2,
                             const float* __restrict__ tv){
    int blk = blockIdx.x, tid = threadIdx.x;
    if (blk < 512){
        const float* w = (blk < 256) ? wih : whh;
        float4* o = (blk < 256) ? g_wihP : g_whhP;
        int idx = (blk & 255) * 256 + tid;          // 0..65535
        int d = idx & 255, e = idx >> 8;
        o[(size_t)e * 256 + d] = make_float4(
            w[(size_t)(0*D_ + d) * D_ + e],
            w[(size_t)(1*D_ + d) * D_ + e],
            w[(size_t)(2*D_ + d) * D_ + e], 0.f);
    } else if (blk < 768){
        int idx = (blk - 512) * 256 + tid;          // 0..65535
        int h = idx & 1023, e4 = idx >> 10;         // e4 0..63
        const float* r = w1 + (size_t)h * D_ + e4 * 4;
        g_w1P[(size_t)e4 * HID_ + h] = make_float4(r[0], r[1], r[2], r[3]);
    } else if (blk < 1024){
        int idx = (blk - 768) * 256 + tid;          // 0..65535
        int d = idx & 255, e4 = idx >> 8;           // e4 0..255
        const float* r = w2 + (size_t)d * HID_ + e4 * 4;
        g_w2P[(size_t)e4 * D_ + d] = make_float4(r[0], r[1], r[2], r[3]);
    } else {
        int idx = (blk - 1024) * 256 + tid;         // 0..131071
        int d = idx & 255;
        int rest = idx >> 8;                        // 0..511
        int e4 = rest & 63, k = rest >> 6;
        const float* base = tv + (size_t)k * D_ * D_ + (size_t)(e4*4) * D_ + d;
        g_tvP[(size_t)k * (64*256) + (size_t)e4 * 256 + d] =
            make_float4(base[0], base[D_], base[2*D_], base[3*D_]);
    }
}

// ---------------------------------------------------------------------------
// k_slotproj: (optionally) finalize slots = sn + b2 + sum of 8 MLP2 partials,
// then s = LN(slots); q = s*diag(tq[k]); wk[b,k,h,e] = sum_{d in h} tk[k,e,d]*q[d]
// ---------------------------------------------------------------------------
__global__ void k_slotproj(float* __restrict__ slots, const float* __restrict__ tq,
                           const float* __restrict__ tk,
                           const float* __restrict__ lng, const float* __restrict__ lnb,
                           const float* __restrict__ b2v, int fuse){
    __shared__ float qs[D_];
    __shared__ float red[32];
    int blk = blockIdx.x;                 // p = b*8 + k
    int b = blk >> 3, k = blk & 7;
    int tid = threadIdx.x, lane = tid & 31, w = tid >> 5;

    float x;
    if (fuse){
        size_t i = (size_t)blk * D_ + tid;
        float v = g_sn[i] + b2v[tid];
#pragma unroll
        for (int s = 0; s < 8; s++) v += g_part[(size_t)s * (PAIRS_*D_) + i];
        slots[i] = v;
        x = v;
    } else {
        x = slots[(size_t)blk * D_ + tid];
    }

    float s = warpSum(x), q2 = warpSum(x * x);
    if (lane == 0){ red[w] = s; red[8 + w] = q2; }
    __syncthreads();
    if (tid == 0){
        float ts = 0.f, tqq = 0.f;
        for (int i = 0; i < 8; i++){ ts += red[i]; tqq += red[8 + i]; }
        float m = ts * (1.0f / D_);
        red[16] = m;
        red[17] = rsqrtf(tqq * (1.0f / D_) - m*m + EPS_);
    }
    __syncthreads();
    float m = red[16], r = red[17];
    float sv = (x - m) * r * lng[tid] + lnb[tid];
    qs[tid] = sv * tq[(size_t)k * D_ * D_ + (size_t)tid * D_ + tid];   // diagonal
    __syncthreads();

    const float* tkk = tk + (size_t)k * D_ * D_;
    for (int ei = 0; ei < 32; ei++){
        int e = w * 32 + ei;
        const float* te = tkk + (size_t)e * D_;
        float p0 = 0.f, p1 = 0.f, p2 = 0.f, p3 = 0.f;
#pragma unroll
        for (int j = 0; j < 8; j++){
            int d = j * 32 + lane;                 // each j lies inside one head
            float v = te[d] * qs[d];
            if (j < 2) p0 += v; else if (j < 4) p1 += v; else if (j < 6) p2 += v; else p3 += v;
        }
        p0 = warpSum(p0); p1 = warpSum(p1); p2 = warpSum(p2); p3 = warpSum(p3);
        if (lane == 0){
            float* wo = g_wk + (size_t)b * 32 * D_ + (size_t)(k * 4) * D_ + e;
            wo[0] = p0; wo[D_] = p1; wo[2 * D_] = p2; wo[3 * D_] = p3;
        }
    }
}

// ---------------------------------------------------------------------------
// k_attn: dots -> softmax over slots -> head-avg -> attn_vis; c + rowsum partials.
// ---------------------------------------------------------------------------
#define TPB 64
#define WPITCH 260
#define APITCH 10

__global__ void __launch_bounds__(256, 2) k_attn(float* __restrict__ attnv){
    extern __shared__ float sm[];
    float* wks  = sm;                       // 32 x 260
    float* embs = sm + 32 * WPITCH;         // 64 x 256
    float* a_s  = embs + TPB * D_;          // 64 x 10

    int b    = blockIdx.x >> 5;
    int tile = blockIdx.x & 31;
    int n0   = tile * TPB;
    int tid = threadIdx.x, lane = tid & 31, w = tid >> 5;

    const float* wg = g_wk + (size_t)b * 32 * D_;
    for (int i = tid; i < 32 * D_; i += 256)
        wks[(i >> 8) * WPITCH + (i & 255)] = wg[i];
    const float4* eg = (const float4*)(g_emb + ((size_t)b * N_ + n0) * D_);
    float4* es4 = (float4*)embs;
    for (int i = tid; i < TPB * D_ / 4; i += 256) es4[i] = eg[i];
    __syncthreads();

    // phase 1: dots (lane owns kh; warp owns 8 tokens); packed over e-pairs
    ull acc[8] = {0,0,0,0,0,0,0,0};
    const float* wrow = wks + lane * WPITCH;
    const float* erow = embs + (w * 8) * D_;
    for (int e = 0; e < D_; e += 4){
        ulonglong2 wv = *(const ulonglong2*)(wrow + e);
#pragma unroll
        for (int j = 0; j < 8; j++){
            ulonglong2 ev = *(const ulonglong2*)(erow + j * D_ + e);
            FMA2(acc[j], wv.x, ev.x);
            FMA2(acc[j], wv.y, ev.y);
        }
    }
    int k = lane >> 2;
#pragma unroll
    for (int j = 0; j < 8; j++){
        float lo, hi;  unpack2(acc[j], lo, hi);
        float d = (lo + hi) * SCALE_;
        float mm = d;
        mm = fmaxf(mm, __shfl_xor_sync(0xffffffffu, mm, 4));
        mm = fmaxf(mm, __shfl_xor_sync(0xffffffffu, mm, 8));
        mm = fmaxf(mm, __shfl_xor_sync(0xffffffffu, mm, 16));
        float p = __expf(d - mm);
        float ssum = p;
        ssum += __shfl_xor_sync(0xffffffffu, ssum, 4);
        ssum += __shfl_xor_sync(0xffffffffu, ssum, 8);
        ssum += __shfl_xor_sync(0xffffffffu, ssum, 16);
        float af = p / ssum;                       // softmax over slots k
        af += __shfl_xor_sync(0xffffffffu, af, 1);
        af += __shfl_xor_sync(0xffffffffu, af, 2); // sum over heads
        if ((lane & 3) == 0) a_s[(w * 8 + j) * APITCH + k] = af * 0.25f;
    }
    __syncthreads();

    // attn_vis
    float* av = attnv + (size_t)b * K_ * N_ + n0;
    for (int i = tid; i < K_ * TPB; i += 256){
        int kk = i >> 6, t = i & 63;
        av[(size_t)kk * N_ + t] = a_s[t * APITCH + kk];
    }

    // rowsum partial: warp w sums slot k=w over the 64 tokens
    {
        float s = a_s[lane * APITCH + w] + a_s[(lane + 32) * APITCH + w];
        s = warpSum(s);
        if (lane == 0) g_rspart[(size_t)(b * 32 + tile) * 8 + w] = s;
    }

    // phase 2: per-tile partial c; warp w owns e = w*32+lane; packed over k-pairs
    int e = w * 32 + lane;
    ull cl2[4] = {0,0,0,0};
    for (int t = 0; t < TPB; t++){
        float ev = embs[t * D_ + e];
        ull ev2;  PACK2(ev2, ev, ev);
        const ull* ar = (const ull*)(a_s + t * APITCH);
        FMA2(cl2[0], ar[0], ev2);
        FMA2(cl2[1], ar[1], ev2);
        FMA2(cl2[2], ar[2], ev2);
        FMA2(cl2[3], ar[3], ev2);
    }
    float* cp = g_cpart + (size_t)tile * (PAIRS_*D_) + (size_t)b * K_ * D_ + e;
#pragma unroll
    for (int m = 0; m < 4; m++){
        float lo, hi;  unpack2(cl2[m], lo, hi);
        cp[(size_t)(2*m) * D_]     = lo;
        cp[(size_t)(2*m + 1) * D_] = hi;
    }
}

// ---------------------------------------------------------------------------
// k_prep: per pair p: rowsum (from tile partials); cn = (sum of c partials)/rs;
//         xs = cn @ tv[k]  (packed tvP, FMA2).
// ---------------------------------------------------------------------------
__global__ void __launch_bounds__(256) k_prep(){
    __shared__ __align__(16) float cn[D_];
    __shared__ float rsh;
    int p = blockIdx.x;
    int b = p >> 3, k = p & 7;
    int tid = threadIdx.x;

    if (tid < 32){
        float r = g_rspart[(size_t)(b * 32 + tid) * 8 + k];
        r = warpSum(r);
        if (tid == 0) rsh = r;
    }
    float c = 0.f;
#pragma unroll 8
    for (int t = 0; t < 32; t++)
        c += g_cpart[(size_t)t * (PAIRS_*D_) + (size_t)p * D_ + tid];
    __syncthreads();
    cn[tid] = c / rsh;
    __syncthreads();

    ull acc = 0;
    const float4* tvp = g_tvP + (size_t)k * (64*256) + tid;
    for (int e4 = 0; e4 < 64; e4++){
        ulonglong2 u = *(const ulonglong2*)(tvp + (size_t)e4 * 256);
        ulonglong2 cv = ((const ulonglong2*)cn)[e4];
        FMA2(acc, u.x, cv.x);
        FMA2(acc, u.y, cv.y);
    }
    float lo, hi;  unpack2(acc, lo, hi);
    g_xs[(size_t)p * D_ + tid] = lo + hi;
}

// ---------------------------------------------------------------------------
// k_gates: grid 128 = 16 groups(=batches) x 8 d-tiles(32).
// thread (bb = tid>>5, d = d0+lane): full GRU output sn. Packed weights + FMA2.
// ---------------------------------------------------------------------------
__global__ void __launch_bounds__(256) k_gates(const float* __restrict__ slots,
                                               const float* __restrict__ bih,
                                               const float* __restrict__ bhh){
    __shared__ float xs[8][D_];
    __shared__ float hs[8][D_];
    int g  = blockIdx.x >> 3;
    int d0 = (blockIdx.x & 7) * 32;
    int tid = threadIdx.x;
    for (int i = tid; i < 8 * D_; i += 256){
        int pp = i >> 8, e = i & 255;
        xs[pp][e] = g_xs[(size_t)(g * 8 + pp) * D_ + e];
        hs[pp][e] = slots[(size_t)(g * 8 + pp) * D_ + e];
    }
    __syncthreads();

    int bb = tid >> 5, d = d0 + (tid & 31);
    ull ai01, ai2, ah01, ah2;
    PACK2(ai01, bih[d], bih[d + D_]);
    PACK2(ai2,  bih[d + 2*D_], 0.f);
    PACK2(ah01, bhh[d], bhh[d + D_]);
    PACK2(ah2,  bhh[d + 2*D_], 0.f);

    const ulonglong2* wi = (const ulonglong2*)(g_wihP + d);
    const ulonglong2* wh = (const ulonglong2*)(g_whhP + d);
#pragma unroll 4
    for (int e = 0; e < D_; e++){
        float xv = xs[bb][e], hv = hs[bb][e];
        ull x2, h2;  PACK2(x2, xv, xv);  PACK2(h2, hv, hv);
        ulonglong2 wiv = wi[(size_t)e * 256];
        ulonglong2 whv = wh[(size_t)e * 256];
        FMA2(ai01, wiv.x, x2);  FMA2(ai2, wiv.y, x2);
        FMA2(ah01, whv.x, h2);  FMA2(ah2, whv.y, h2);
    }
    float gi0, gi1, gi2, gh0, gh1, gh2, dump;
    unpack2(ai01, gi0, gi1);  unpack2(ai2, gi2, dump);
    unpack2(ah01, gh0, gh1);  unpack2(ah2, gh2, dump);
    float r = 1.f / (1.f + __expf(-(gi0 + gh0)));
    float z = 1.f / (1.f + __expf(-(gi1 + gh1)));
    float n = tanhf(gi2 + r * gh2);
    g_sn[(size_t)(g * 8 + bb) * D_ + d] = (1.f - z) * n + z * hs[bb][d];
}

// ---------------------------------------------------------------------------
// k_mlp1: grid 128 = 16 groups x 8 h-tiles(128). LN_ff in-block, hidden GEMM.
// thread: h = h0 + (tid&127), pair-half = tid>>7 (4 pairs each).
// ---------------------------------------------------------------------------
__global__ void __launch_bounds__(256) k_mlp1(const float* __restrict__ b1v,
                                              const float* __restrict__ ffg,
                                              const float* __restrict__ ffb){
    __shared__ __align__(16) float ps[8][D_];
    int g  = blockIdx.x >> 3;
    int h0 = (blockIdx.x & 7) * 128;
    int tid = threadIdx.x, lane = tid & 31, w = tid >> 5;

    // warp w LayerNorms row (g*8 + w)
    {
        const float4* xr = (const float4*)(g_sn + (size_t)(g * 8 + w) * D_);
        float4 a = xr[lane], c = xr[lane + 32];
        float s = a.x+a.y+a.z+a.w + c.x+c.y+c.z+c.w;
        float q = a.x*a.x+a.y*a.y+a.z*a.z+a.w*a.w + c.x*c.x+c.y*c.y+c.z*c.z+c.w*c.w;
        s = warpSum(s); q = warpSum(q);
        float m = s * (1.0f / D_);
        float r = rsqrtf(q * (1.0f / D_) - m*m + EPS_);
        float4 ga = ((const float4*)ffg)[lane],  gc = ((const float4*)ffg)[lane + 32];
        float4 ba = ((const float4*)ffb)[lane],  bc = ((const float4*)ffb)[lane + 32];
        float4 oa, oc;
        oa.x = (a.x-m)*r*ga.x + ba.x;  oa.y = (a.y-m)*r*ga.y + ba.y;
        oa.z = (a.z-m)*r*ga.z + ba.z;  oa.w = (a.w-m)*r*ga.w + ba.w;
        oc.x = (c.x-m)*r*gc.x + bc.x;  oc.y = (c.y-m)*r*gc.y + bc.y;
        oc.z = (c.z-m)*r*gc.z + bc.z;  oc.w = (c.w-m)*r*gc.w + bc.w;
        ((float4*)ps[w])[lane] = oa;  ((float4*)ps[w])[lane + 32] = oc;
    }
    __syncthreads();

    int h = h0 + (tid & 127);
    int ph = (tid >> 7) * 4;                    // pair base (0 or 4)
    ull acc[4] = {0,0,0,0};
    const ulonglong2* w1p = (const ulonglong2*)(g_w1P + h);
    for (int e4 = 0; e4 < 64; e4++){
        ulonglong2 wq = w1p[(size_t)e4 * HID_];
#pragma unroll
        for (int pp = 0; pp < 4; pp++){
            ulonglong2 pv = ((const ulonglong2*)ps[ph + pp])[e4];
            FMA2(acc[pp], wq.x, pv.x);
            FMA2(acc[pp], wq.y, pv.y);
        }
    }
    float bv = b1v[h];
#pragma unroll
    for (int pp = 0; pp < 4; pp++){
        float lo, hi;  unpack2(acc[pp], lo, hi);
        g_hid[(size_t)(g * 8 + ph + pp) * HID_ + h] = fmaxf(lo + hi + bv, 0.f);
    }
}

// ---------------------------------------------------------------------------
// k_mlp2: grid 128 = 16 groups x 8 e-splits(128). Deterministic partials.
// ---------------------------------------------------------------------------
__global__ void __launch_bounds__(256) k_mlp2(){
    __shared__ __align__(16) float hd[8][128];
    int g  = blockIdx.x >> 3;
    int ks = blockIdx.x & 7;
    int e0 = ks * 128;
    int tid = threadIdx.x;
    for (int i = tid; i < 8 * 128; i += 256){
        int pp = i >> 7, e = i & 127;
        hd[pp][e] = g_hid[(size_t)(g * 8 + pp) * HID_ + e0 + e];
    }
    __syncthreads();

    int d = tid;
    ull acc[8] = {0,0,0,0,0,0,0,0};
    const ulonglong2* w2p = (const ulonglong2*)(g_w2P + (size_t)(e0/4) * D_ + d);
    for (int e4 = 0; e4 < 32; e4++){
        ulonglong2 wq = w2p[(size_t)e4 * D_];
#pragma unroll
        for (int pp = 0; pp < 8; pp++){
            ulonglong2 hv = ((const ulonglong2*)hd[pp])[e4];
            FMA2(acc[pp], wq.x, hv.x);
            FMA2(acc[pp], wq.y, hv.y);
        }
    }
#pragma unroll
    for (int pp = 0; pp < 8; pp++){
        float lo, hi;  unpack2(acc[pp], lo, hi);
        g_part[(size_t)ks * (PAIRS_*D_) + (size_t)(g * 8 + pp) * D_ + d] = lo + hi;
    }
}

// ---------------------------------------------------------------------------
// k_fin (once, after last iter): slots = sn + b2 + sum of 8 partials
// ---------------------------------------------------------------------------
__global__ void k_fin(float* __restrict__ slots, const float* __restrict__ b2v){
    int p = blockIdx.x, d = threadIdx.x;
    size_t i = (size_t)p * D_ + d;
    float v = g_sn[i] + b2v[d];
#pragma unroll
    for (int s = 0; s < 8; s++) v += g_part[(size_t)s * (PAIRS_*D_) + i];
    slots[i] = v;
}

// ---------------------------------------------------------------------------
extern "C" void kernel_launch(void* const* d_in, const int* in_sizes, int n_in,
                              void* d_out, int out_size){
    const float* emb  = (const float*)d_in[0];
    const float* noise= (const float*)d_in[1];
    const float* mu   = (const float*)d_in[2];
    const float* ls   = (const float*)d_in[3];
    const float* tk   = (const float*)d_in[4];
    const float* tq   = (const float*)d_in[5];
    const float* tv   = (const float*)d_in[6];
    const float* wih  = (const float*)d_in[7];
    const float* whh  = (const float*)d_in[8];
    const float* bih  = (const float*)d_in[9];
    const float* bhh  = (const float*)d_in[10];
    const float* w1   = (const float*)d_in[11];
    const float* b1   = (const float*)d_in[12];
    const float* w2   = (const float*)d_in[13];
    const float* b2   = (const float*)d_in[14];
    const float* ling = (const float*)d_in[15];
    const float* linb = (const float*)d_in[16];
    const float* lslg = (const float*)d_in[17];
    const float* lslb = (const float*)d_in[18];
    const float* lffg = (const float*)d_in[19];
    const float* lffb = (const float*)d_in[20];

    float* slots = (float*)d_out;               // (B,K,D)
    float* attnv = slots + B_*K_*D_;            // (B,K,N)

    const int smemB = (32 * WPITCH + TPB * D_ + TPB * APITCH) * 4;   // ~99 KB
    cudaFuncSetAttribute(k_attn, cudaFuncAttributeMaxDynamicSharedMemorySize, smemB);

    k_setup_a<<<4224, 256>>>(emb, ling, linb, mu, ls, noise, slots);
    k_setup_pack<<<1536, 256>>>(wih, whh, w1, w2, tv);

    for (int it = 0; it < ITERS_; it++){
        k_slotproj<<<PAIRS_, 256>>>(slots, tq, tk, lslg, lslb, b2, it > 0 ? 1 : 0);
        k_attn<<<B_*NTILES_, 256, smemB>>>(attnv);
        k_prep<<<PAIRS_, 256>>>();
        k_gates<<<128, 256>>>(slots, bih, bhh);
        k_mlp1<<<128, 256>>>(b1, lffg, lffb);
        k_mlp2<<<128, 256>>>();
    }
    k_fin<<<PAIRS_, 256>>>(slots, b2);
}